// round 12
// baseline (speedup 1.0000x reference)
#include <cuda_runtime.h>
#include <cstdint>
#include <cstddef>

#define NPTS   65536
#define CHN    512
#define C3     1536
#define PSZ    256
#define NHEAD  8
#define DHEAD  64
#define NBATCH 4
#define NCHUNK (NPTS / PSZ)   // 256

#define ATT_SCALE (0.125f * 1.44269504088896340736f)

// K-permutation within each 32-block (applied to ALL GEMM K-dim layouts):
// smem/global word p holds original k(p) = ((p>>1)&3)*8 + (p>>3) + 4*(p&1)
// inverse: p(k) = (k&3)*8 + (k>>3)*2 + ((k>>2)&1)
__device__ __forceinline__ int kperm(int k) {
    return (k & 3) * 8 + ((k >> 3) & 3) * 2 + ((k >> 2) & 1);
}

// ---------------- scratch (device globals: allocation-free) ----------------
__device__ float g_qkv[(size_t)NPTS * C3];       // serialized-order qkv (tf32-rounded)
__device__ float g_outp[(size_t)NPTS * CHN];     // attention out (tf32-rounded, k-permuted)
__device__ float g_featc[(size_t)NPTS * CHN];    // tf32-rounded feat (k-permuted)
__device__ float g_wqkvt[(size_t)C3 * CHN];      // tf32 Wqkv^T [1536][512] (k-permuted)
__device__ float g_wprojt[(size_t)CHN * CHN];    // tf32 Wproj^T [512][512] (k-permuted)
__device__ float g_cls_out[NCHUNK * CHN];
__device__ float g_cls_qkv[NBATCH * C3];

__device__ __forceinline__ uint32_t f2tf32(float f) {
    uint32_t u;
    asm("cvt.rna.tf32.f32 %0, %1;" : "=r"(u) : "f"(f));
    return u;
}
__device__ __forceinline__ float rnd_tf32(float f) {
    return __uint_as_float(f2tf32(f));
}

__device__ __forceinline__ void mma_tf32(float* c, uint32_t a0, uint32_t a1,
                                         uint32_t a2, uint32_t a3,
                                         uint32_t b0, uint32_t b1) {
    asm volatile(
        "mma.sync.aligned.m16n8k8.row.col.f32.tf32.tf32.f32 "
        "{%0,%1,%2,%3}, {%4,%5,%6,%7}, {%8,%9}, {%0,%1,%2,%3};"
        : "+f"(c[0]), "+f"(c[1]), "+f"(c[2]), "+f"(c[3])
        : "r"(a0), "r"(a1), "r"(a2), "r"(a3), "r"(b0), "r"(b1));
}

__device__ __forceinline__ void cp16(uint32_t smem_addr, const void* gptr) {
    asm volatile("cp.async.cg.shared.global [%0], [%1], 16;"
                 :: "r"(smem_addr), "l"(gptr) : "memory");
}
__device__ __forceinline__ void cp_commit() {
    asm volatile("cp.async.commit_group;" ::: "memory");
}
template <int N>
__device__ __forceinline__ void cp_wait() {
    asm volatile("cp.async.wait_group %0;" :: "n"(N) : "memory");
}

// ---------------- K0a: tf32 round + k-permute copy (feat) ----------------
// out word blk*32+p = rnd(in word blk*32+k(p)); one float4 of p covers
// k = 16c + t + {0,4,8,12} with t=(q>>1), c=(q&1), q = float4-index in block.
__global__ void cvt_perm_kernel(const float* __restrict__ in,
                                float* __restrict__ out, int n4) {
    int i = blockIdx.x * blockDim.x + threadIdx.x;
    if (i >= n4) return;
    int blk = i >> 3, q = i & 7;
    int t = q >> 1, c = q & 1;
    const float* src = in + blk * 32 + 16 * c + t;
    float4 v;
    v.x = rnd_tf32(src[0]);
    v.y = rnd_tf32(src[4]);
    v.z = rnd_tf32(src[8]);
    v.w = rnd_tf32(src[12]);
    ((float4*)out)[i] = v;
}

// ---------------- K0b: transpose + tf32 round + k-permute (weights) --------
// in [K][N] row-major -> out [N][K] with K permuted per 32-block
__global__ void transpose_tf32_kernel(const float* __restrict__ in,
                                      float* __restrict__ out, int K, int N) {
    __shared__ float t[32][33];
    const int x = threadIdx.x, y = threadIdx.y;
    const int bx = blockIdx.x, by = blockIdx.y;
    #pragma unroll
    for (int i = 0; i < 32; i += 8)
        t[y + i][x] = in[(size_t)(by * 32 + y + i) * N + bx * 32 + x];
    __syncthreads();
    const int px = kperm(x);   // x = original k within block -> permuted pos
    #pragma unroll
    for (int i = 0; i < 32; i += 8)
        out[(size_t)(bx * 32 + y + i) * K + by * 32 + px] = rnd_tf32(t[x][y + i]);
}

// ---------------- K1: cls_qkv (warp per output, split-K) ----------------
__global__ __launch_bounds__(256)
void cls_qkv_kernel(const float* __restrict__ cls_tokens,
                    const float* __restrict__ Wqkv,
                    const float* __restrict__ bqkv,
                    float* __restrict__ cls_qkv) {
    const int w = blockIdx.x * 8 + (threadIdx.x >> 5);
    const int lane = threadIdx.x & 31;
    const int b = w / C3, o = w - b * C3;
    float s = 0.f;
    #pragma unroll
    for (int k = lane; k < CHN; k += 32)
        s += cls_tokens[b * CHN + k] * Wqkv[(size_t)k * C3 + o];
    #pragma unroll
    for (int d = 16; d >= 1; d >>= 1)
        s += __shfl_xor_sync(0xffffffffu, s, d);
    if (lane == 0) cls_qkv[w] = rnd_tf32(s + bqkv[o]);
}

// ------ tf32 GEMM: 128x128x32, 256 thr, cp.async 3-stage, LDS.128 frags ----
// A [M][K] and Bt [N][K], both K-major, tf32-rounded, K-PERMUTED per 32-block.
// Smem: per stage, A-tile and B-tile each [128 rows][32 words], stride 36.
#define TS 36
#define MAT_WORDS (128 * TS)               // 4608
#define STAGE_WORDS (2 * MAT_WORDS)        // 9216
#define NSTAGE 3
#define GEMM_SMEM (NSTAGE * STAGE_WORDS * 4)   // 110592 bytes

template <int MODE>   // 0: scatter rows by rowmap + tf32-round out; 1: direct
__global__ __launch_bounds__(256, 2)
void tgemm_kernel(const float* __restrict__ A, const float* __restrict__ Bt,
                  const float* __restrict__ bias, float* __restrict__ Cout,
                  const int* __restrict__ rowmap,
                  int Kdim, int ldc) {
    extern __shared__ float smf[];
    uint32_t* Sm = (uint32_t*)smf;

    const int tid  = threadIdx.x;
    const int lane = tid & 31;
    const int warp = tid >> 5;
    const int wm   = warp >> 2;
    const int wn   = warp & 3;
    const int g    = lane >> 2;
    const int t    = lane & 3;

    const int f_row = tid >> 1;            // 0..127
    const int f_k0  = (tid & 1) * 16;      // 0 or 16
    const float* Ag = A  + (size_t)(blockIdx.y * 128 + f_row) * Kdim + f_k0;
    const float* Bg = Bt + (size_t)(blockIdx.x * 128 + f_row) * Kdim + f_k0;
    const uint32_t sa_base = (uint32_t)__cvta_generic_to_shared(Sm) +
                             (uint32_t)((f_row * TS + f_k0) * 4);

    auto issue = [&](int kt) {
        const uint32_t sd = sa_base + (kt % NSTAGE) * (STAGE_WORDS * 4);
        const float* ag = Ag + kt * 32;
        const float* bg = Bg + kt * 32;
        #pragma unroll
        for (int i = 0; i < 4; i++) {
            cp16(sd + i * 16,                  ag + i * 4);
            cp16(sd + MAT_WORDS * 4 + i * 16,  bg + i * 4);
        }
        cp_commit();
    };

    const int nk = Kdim >> 5;
    issue(0); issue(1);

    float c[4][4][4];
    #pragma unroll
    for (int mi = 0; mi < 4; mi++)
        #pragma unroll
        for (int ni = 0; ni < 4; ni++)
            #pragma unroll
            for (int r = 0; r < 4; r++) c[mi][ni][r] = 0.f;

    for (int kt = 0; kt < nk; kt++) {
        const int cur = kt % NSTAGE;
        if (kt + 1 < nk) cp_wait<1>(); else cp_wait<0>();
        __syncthreads();
        if (kt + 2 < nk) issue(kt + 2);

        const uint32_t* asb = Sm + cur * STAGE_WORDS;
        const uint32_t* bsb = asb + MAT_WORDS;
        // k-tile processed as 2 half-tiles (ksp): each fragment row is one
        // LDS.128 thanks to the global K-permutation.
        #pragma unroll
        for (int ksp = 0; ksp < 2; ksp++) {
            const int co = t * 8 + ksp * 4;
            uint4 bv[4];
            #pragma unroll
            for (int ni = 0; ni < 4; ni++)
                bv[ni] = *(const uint4*)&bsb[(wn * 32 + ni * 8 + g) * TS + co];
            #pragma unroll
            for (int mi = 0; mi < 4; mi++) {
                const int row = wm * 64 + mi * 16 + g;
                uint4 alo = *(const uint4*)&asb[(row)     * TS + co];
                uint4 ahi = *(const uint4*)&asb[(row + 8) * TS + co];
                #pragma unroll
                for (int ni = 0; ni < 4; ni++)
                    mma_tf32(c[mi][ni], alo.x, ahi.x, alo.y, ahi.y,
                             bv[ni].x, bv[ni].y);
                #pragma unroll
                for (int ni = 0; ni < 4; ni++)
                    mma_tf32(c[mi][ni], alo.z, ahi.z, alo.w, ahi.w,
                             bv[ni].z, bv[ni].w);
            }
        }
    }

    float2 bvb[4];
    #pragma unroll
    for (int ni = 0; ni < 4; ni++)
        bvb[ni] = *(const float2*)&bias[blockIdx.x * 128 + wn * 32 + ni * 8 + t * 2];

    #pragma unroll
    for (int mi = 0; mi < 4; mi++) {
        const int m0 = blockIdx.y * 128 + wm * 64 + mi * 16 + g;
        const int r0 = (MODE == 0) ? rowmap[m0]     : m0;
        const int r1 = (MODE == 0) ? rowmap[m0 + 8] : m0 + 8;
        #pragma unroll
        for (int ni = 0; ni < 4; ni++) {
            const int col = blockIdx.x * 128 + wn * 32 + ni * 8 + t * 2;
            float2 v0 = make_float2(c[mi][ni][0] + bvb[ni].x, c[mi][ni][1] + bvb[ni].y);
            float2 v1 = make_float2(c[mi][ni][2] + bvb[ni].x, c[mi][ni][3] + bvb[ni].y);
            if (MODE == 0) {
                v0.x = rnd_tf32(v0.x); v0.y = rnd_tf32(v0.y);
                v1.x = rnd_tf32(v1.x); v1.y = rnd_tf32(v1.y);
            }
            *(float2*)(Cout + (size_t)r0 * ldc + col) = v0;
            *(float2*)(Cout + (size_t)r1 * ldc + col) = v1;
        }
    }
}

// ---------------- K3: tensor-core flash attention ----------
// outp (proj's A) is stored with K-PERMUTED columns per 32-block.
#define KT_STRIDE 264
#define VS_STRIDE 72
#define QS_STRIDE 72
#define KT_WORDS (64 * KT_STRIDE)
#define VS_WORDS (264 * VS_STRIDE)
#define QS_WORDS (256 * QS_STRIDE)
#define AT_SMEM ((KT_WORDS + VS_WORDS + QS_WORDS) * 4)   // 217344 bytes

__global__ __launch_bounds__(512)
void attn_tc_kernel(const float* __restrict__ qkv,
                    const float* __restrict__ cls_qkv,
                    const int* __restrict__ order,
                    const int* __restrict__ offset,
                    float* __restrict__ outp,
                    float* __restrict__ cls_out) {
    extern __shared__ uint32_t sm[];
    uint32_t* Kt = sm;
    uint32_t* Vs = sm + KT_WORDS;
    uint32_t* Qs = sm + KT_WORDS + VS_WORDS;

    __shared__ float cq[64];
    __shared__ float cps[257];
    __shared__ float cpart[512];
    __shared__ float cinv;

    const int chunk = blockIdx.x >> 3;
    const int head  = blockIdx.x & 7;
    const int tid   = threadIdx.x;

    const int start = chunk * PSZ;
    const int bid = (start >= offset[0]) + (start >= offset[1]) +
                    (start >= offset[2]) + (start >= offset[3]);
    const float* clsrow = cls_qkv + (size_t)bid * C3;

    for (int e = tid; e < 64 * 7; e += 512) {
        int d = e / 7, k = e % 7;
        Kt[d * KT_STRIDE + 257 + k] = 0;
    }
    for (int e = tid; e < 7 * VS_STRIDE; e += 512)
        Vs[257 * VS_STRIDE + e] = 0;

    for (int key = tid; key < 257; key += 512) {
        const float* base = (key < 256)
            ? qkv + (size_t)(chunk * PSZ + key) * C3 : clsrow;
        #pragma unroll
        for (int d4 = 0; d4 < 16; d4++) {
            float4 kv = *(const float4*)(base + CHN + head * DHEAD + d4 * 4);
            Kt[(d4 * 4 + 0) * KT_STRIDE + key] = __float_as_uint(kv.x);
            Kt[(d4 * 4 + 1) * KT_STRIDE + key] = __float_as_uint(kv.y);
            Kt[(d4 * 4 + 2) * KT_STRIDE + key] = __float_as_uint(kv.z);
            Kt[(d4 * 4 + 3) * KT_STRIDE + key] = __float_as_uint(kv.w);
        }
    }
    for (int e = tid; e < 257 * 16; e += 512) {
        int key = e >> 4, d4 = e & 15;
        const float* base = (key < 256)
            ? qkv + (size_t)(chunk * PSZ + key) * C3 : clsrow;
        float4 vv = *(const float4*)(base + 2 * CHN + head * DHEAD + d4 * 4);
        uint32_t* dst = Vs + key * VS_STRIDE + d4 * 4;
        dst[0] = __float_as_uint(vv.x); dst[1] = __float_as_uint(vv.y);
        dst[2] = __float_as_uint(vv.z); dst[3] = __float_as_uint(vv.w);
    }
    for (int e = tid; e < 256 * 16; e += 512) {
        int i = e >> 4, d4 = e & 15;
        const float* base = qkv + (size_t)(chunk * PSZ + i) * C3;
        float4 qv = *(const float4*)(base + head * DHEAD + d4 * 4);
        uint32_t* dst = Qs + i * QS_STRIDE + d4 * 4;
        dst[0] = f2tf32(qv.x * ATT_SCALE);
        dst[1] = f2tf32(qv.y * ATT_SCALE);
        dst[2] = f2tf32(qv.z * ATT_SCALE);
        dst[3] = f2tf32(qv.w * ATT_SCALE);
    }
    if (tid < 64) cq[tid] = clsrow[head * DHEAD + tid] * ATT_SCALE;
    __syncthreads();

    const int warp = tid >> 5, lane = tid & 31;
    const int g = lane >> 2, t = lane & 3;
    const int mrow = warp * 16;

    uint32_t qf[8][4];
    #pragma unroll
    for (int ks = 0; ks < 8; ks++) {
        qf[ks][0] = Qs[(mrow + g)     * QS_STRIDE + ks * 8 + t];
        qf[ks][1] = Qs[(mrow + g + 8) * QS_STRIDE + ks * 8 + t];
        qf[ks][2] = Qs[(mrow + g)     * QS_STRIDE + ks * 8 + t + 4];
        qf[ks][3] = Qs[(mrow + g + 8) * QS_STRIDE + ks * 8 + t + 4];
    }
    __syncwarp();

    float o[8][4];
    #pragma unroll
    for (int nt = 0; nt < 8; nt++)
        #pragma unroll
        for (int r = 0; r < 4; r++) o[nt][r] = 0.f;
    float m0 = -1e30f, m1 = -1e30f, l0 = 0.f, l1 = 0.f;

    for (int kb = 0; kb < 5; kb++) {
        const int nnt = (kb < 4) ? 8 : 1;
        float s[8][4];
        #pragma unroll
        for (int nt = 0; nt < 8; nt++)
            #pragma unroll
            for (int r = 0; r < 4; r++) s[nt][r] = 0.f;

        #pragma unroll
        for (int ks = 0; ks < 8; ks++) {
            #pragma unroll
            for (int nt = 0; nt < 8; nt++) {
                if (nt >= nnt) break;
                uint32_t b0 = Kt[(ks * 8 + t)     * KT_STRIDE + kb * 64 + nt * 8 + g];
                uint32_t b1 = Kt[(ks * 8 + t + 4) * KT_STRIDE + kb * 64 + nt * 8 + g];
                mma_tf32(s[nt], qf[ks][0], qf[ks][1], qf[ks][2], qf[ks][3], b0, b1);
            }
        }
        if (kb == 4) {
            if (t != 0) { s[0][0] = -1e30f; s[0][2] = -1e30f; }
            s[0][1] = -1e30f; s[0][3] = -1e30f;
        }

        float mx0 = -1e30f, mx1 = -1e30f;
        #pragma unroll
        for (int nt = 0; nt < 8; nt++) {
            if (nt >= nnt) break;
            mx0 = fmaxf(mx0, fmaxf(s[nt][0], s[nt][1]));
            mx1 = fmaxf(mx1, fmaxf(s[nt][2], s[nt][3]));
        }
        mx0 = fmaxf(mx0, __shfl_xor_sync(0xffffffffu, mx0, 1));
        mx0 = fmaxf(mx0, __shfl_xor_sync(0xffffffffu, mx0, 2));
        mx1 = fmaxf(mx1, __shfl_xor_sync(0xffffffffu, mx1, 1));
        mx1 = fmaxf(mx1, __shfl_xor_sync(0xffffffffu, mx1, 2));
        float nm0 = fmaxf(m0, mx0), nm1 = fmaxf(m1, mx1);
        float f0 = exp2f(m0 - nm0), f1 = exp2f(m1 - nm1);
        m0 = nm0; m1 = nm1; l0 *= f0; l1 *= f1;
        #pragma unroll
        for (int nt = 0; nt < 8; nt++) {
            o[nt][0] *= f0; o[nt][1] *= f0;
            o[nt][2] *= f1; o[nt][3] *= f1;
        }
        #pragma unroll
        for (int nt = 0; nt < 8; nt++) {
            if (nt >= nnt) break;
            float p0 = exp2f(s[nt][0] - m0), p1 = exp2f(s[nt][1] - m0);
            float p2 = exp2f(s[nt][2] - m1), p3 = exp2f(s[nt][3] - m1);
            l0 += p0 + p1; l1 += p2 + p3;
            Qs[(mrow + g)     * QS_STRIDE + nt * 8 + 2 * t]     = f2tf32(p0);
            Qs[(mrow + g)     * QS_STRIDE + nt * 8 + 2 * t + 1] = f2tf32(p1);
            Qs[(mrow + g + 8) * QS_STRIDE + nt * 8 + 2 * t]     = f2tf32(p2);
            Qs[(mrow + g + 8) * QS_STRIDE + nt * 8 + 2 * t + 1] = f2tf32(p3);
        }
        __syncwarp();

        const int nks = (kb < 4) ? 8 : 1;
        #pragma unroll
        for (int ks = 0; ks < 8; ks++) {
            if (ks >= nks) break;
            uint32_t pf[4];
            pf[0] = Qs[(mrow + g)     * QS_STRIDE + ks * 8 + t];
            pf[1] = Qs[(mrow + g + 8) * QS_STRIDE + ks * 8 + t];
            pf[2] = Qs[(mrow + g)     * QS_STRIDE + ks * 8 + t + 4];
            pf[3] = Qs[(mrow + g + 8) * QS_STRIDE + ks * 8 + t + 4];
            #pragma unroll
            for (int nt = 0; nt < 8; nt++) {
                uint32_t b0 = Vs[(kb * 64 + ks * 8 + t)     * VS_STRIDE + nt * 8 + g];
                uint32_t b1 = Vs[(kb * 64 + ks * 8 + t + 4) * VS_STRIDE + nt * 8 + g];
                mma_tf32(o[nt], pf[0], pf[1], pf[2], pf[3], b0, b1);
            }
        }
        __syncwarp();
    }

    l0 += __shfl_xor_sync(0xffffffffu, l0, 1);
    l0 += __shfl_xor_sync(0xffffffffu, l0, 2);
    l1 += __shfl_xor_sync(0xffffffffu, l1, 1);
    l1 += __shfl_xor_sync(0xffffffffu, l1, 2);
    const float inv0 = 1.f / l0, inv1 = 1.f / l1;

    const int q0 = chunk * PSZ + mrow + g;
    const int dr0 = order[q0];
    const int dr1 = order[q0 + 8];
    #pragma unroll
    for (int nt = 0; nt < 8; nt++) {
        const int colk = head * DHEAD + nt * 8 + 2 * t;   // original column
        const int cb = colk & ~31;
        const int p0 = kperm(colk & 31);
        const int p1 = kperm((colk & 31) + 1);
        outp[(size_t)dr0 * CHN + cb + p0] = rnd_tf32(o[nt][0] * inv0);
        outp[(size_t)dr0 * CHN + cb + p1] = rnd_tf32(o[nt][1] * inv0);
        outp[(size_t)dr1 * CHN + cb + p0] = rnd_tf32(o[nt][2] * inv1);
        outp[(size_t)dr1 * CHN + cb + p1] = rnd_tf32(o[nt][3] * inv1);
    }

    // ---- cls-query attention epilogue ----
    __syncthreads();
    for (int key = tid; key < 257; key += 512) {
        float s = 0.f;
        #pragma unroll
        for (int d = 0; d < 64; d++)
            s += cq[d] * __uint_as_float(Kt[d * KT_STRIDE + key]);
        cps[key] = s;
    }
    __syncthreads();
    if (tid < 32) {
        float mx = -1e30f;
        for (int j = tid; j < 257; j += 32) mx = fmaxf(mx, cps[j]);
        #pragma unroll
        for (int d = 16; d >= 1; d >>= 1)
            mx = fmaxf(mx, __shfl_xor_sync(0xffffffffu, mx, d));
        float sum = 0.f;
        for (int j = tid; j < 257; j += 32) {
            float p = exp2f(cps[j] - mx);
            cps[j] = p;
            sum += p;
        }
        #pragma unroll
        for (int d = 16; d >= 1; d >>= 1)
            sum += __shfl_xor_sync(0xffffffffu, sum, d);
        if (tid == 0) cinv = 1.f / sum;
    }
    __syncthreads();
    {
        const int d = tid & 63, q = tid >> 6;
        float a = 0.f;
        for (int j = q; j < 257; j += 8)
            a += cps[j] * __uint_as_float(Vs[j * VS_STRIDE + d]);
        cpart[tid] = a;
    }
    __syncthreads();
    if (tid < 64) {
        float a = 0.f;
        #pragma unroll
        for (int q = 0; q < 8; q++) a += cpart[q * 64 + tid];
        cls_out[(size_t)chunk * CHN + head * DHEAD + tid] = a * cinv;
    }
}

// ---------------- K5: cls_feat = per-batch mean of cls_out ------------
__global__ void cls_feat_kernel(const float* __restrict__ cls_out,
                                const int* __restrict__ offset,
                                float* __restrict__ out) {
    int b = blockIdx.x;
    int c = threadIdx.x;
    int o0 = offset[0], o1 = offset[1], o2 = offset[2], o3 = offset[3];
    float s = 0.f, cnt = 0.f;
    for (int ch = 0; ch < NCHUNK; ch++) {
        int start = ch * PSZ;
        int bid = (start >= o0) + (start >= o1) + (start >= o2) + (start >= o3);
        if (bid == b) { s += cls_out[(size_t)ch * CHN + c]; cnt += 1.f; }
    }
    out[(size_t)b * CHN + c] = s / cnt;
}

// ---------------- launch ----------------
extern "C" void kernel_launch(void* const* d_in, const int* in_sizes, int n_in,
                              void* d_out, int out_size) {
    const float* feat       = (const float*)d_in[0];
    const float* cls_tokens = (const float*)d_in[1];
    const float* Wqkv       = (const float*)d_in[2];
    const float* bqkv       = (const float*)d_in[3];
    const float* Wproj      = (const float*)d_in[4];
    const float* bproj      = (const float*)d_in[5];
    const int*   order      = (const int*)d_in[6];
    const int*   inverse    = (const int*)d_in[7];
    const int*   offset     = (const int*)d_in[8];
    float* out = (float*)d_out;

    float *qkv_p, *outp_p, *clsout_p, *clsqkv_p, *featc_p, *wqkvt_p, *wprojt_p;
    cudaGetSymbolAddress((void**)&qkv_p, g_qkv);
    cudaGetSymbolAddress((void**)&outp_p, g_outp);
    cudaGetSymbolAddress((void**)&clsout_p, g_cls_out);
    cudaGetSymbolAddress((void**)&clsqkv_p, g_cls_qkv);
    cudaGetSymbolAddress((void**)&featc_p, g_featc);
    cudaGetSymbolAddress((void**)&wqkvt_p, g_wqkvt);
    cudaGetSymbolAddress((void**)&wprojt_p, g_wprojt);

    cudaFuncSetAttribute(tgemm_kernel<0>, cudaFuncAttributeMaxDynamicSharedMemorySize, GEMM_SMEM);
    cudaFuncSetAttribute(tgemm_kernel<1>, cudaFuncAttributeMaxDynamicSharedMemorySize, GEMM_SMEM);
    cudaFuncSetAttribute(attn_tc_kernel, cudaFuncAttributeMaxDynamicSharedMemorySize, AT_SMEM);

    // K0: tf32 pre-rounding + K-permute (feat), transpose+round+permute (weights)
    {
        int n4 = NPTS * CHN / 4;
        cvt_perm_kernel<<<(n4 + 255) / 256, 256>>>(feat, featc_p, n4);
        transpose_tf32_kernel<<<dim3(C3 / 32, CHN / 32), dim3(32, 8)>>>(Wqkv, wqkvt_p, CHN, C3);
        transpose_tf32_kernel<<<dim3(CHN / 32, CHN / 32), dim3(32, 8)>>>(Wproj, wprojt_p, CHN, CHN);
    }

    // K1: cls qkv
    cls_qkv_kernel<<<NBATCH * C3 / 8, 256>>>(cls_tokens, Wqkv, bqkv, clsqkv_p);

    // K2: qkv = feat @ Wqkv + bqkv, scattered by inverse, tf32-rounded output
    tgemm_kernel<0><<<dim3(C3 / 128, NPTS / 128), 256, GEMM_SMEM>>>(
        featc_p, wqkvt_p, bqkv, qkv_p, inverse, CHN, C3);

    // K3: flash attention (256 point queries + cls query per block)
    attn_tc_kernel<<<NCHUNK * NHEAD, 512, AT_SMEM>>>(
        qkv_p, clsqkv_p, order, offset, outp_p, clsout_p);

    // K4: feat_out = outp @ Wproj + bproj
    tgemm_kernel<1><<<dim3(CHN / 128, NPTS / 128), 256, GEMM_SMEM>>>(
        outp_p, wprojt_p, bproj, out, nullptr, CHN, CHN);

    // K5: cls_feat
    cls_feat_kernel<<<NBATCH, CHN>>>(clsout_p, offset, out + (size_t)NPTS * CHN);
}

// round 14
// speedup vs baseline: 1.1669x; 1.1669x over previous
#include <cuda_runtime.h>
#include <cstdint>
#include <cstddef>

#define NPTS   65536
#define CHN    512
#define C3     1536
#define PSZ    256
#define NHEAD  8
#define DHEAD  64
#define NBATCH 4
#define NCHUNK (NPTS / PSZ)   // 256

// log2(e) folded into the attention scale: softmax uses exp2
#define ATT_SCALE (0.125f * 1.44269504088896340736f)

// ---------------- scratch (device globals: allocation-free) ----------------
__device__ float g_qkv[(size_t)NPTS * C3];       // serialized-order qkv (tf32-rounded)
__device__ float g_outp[(size_t)NPTS * CHN];     // attention out (tf32-rounded)
__device__ float g_featc[(size_t)NPTS * CHN];    // tf32-rounded feat (PAIR-PERMUTED k)
__device__ float g_wqkvc[(size_t)CHN * C3];      // tf32-rounded Wqkv
__device__ float g_wprojc[(size_t)CHN * CHN];    // tf32-rounded Wproj
__device__ float g_cls_out[NCHUNK * CHN];
__device__ float g_cls_qkv[NBATCH * C3];

__device__ __forceinline__ uint32_t f2tf32(float f) {
    uint32_t u;
    asm("cvt.rna.tf32.f32 %0, %1;" : "=r"(u) : "f"(f));
    return u;
}
__device__ __forceinline__ float rnd_tf32(float f) {
    return __uint_as_float(f2tf32(f));
}

__device__ __forceinline__ void mma_tf32(float* c, const uint32_t* a,
                                         uint32_t b0, uint32_t b1) {
    asm volatile(
        "mma.sync.aligned.m16n8k8.row.col.f32.tf32.tf32.f32 "
        "{%0,%1,%2,%3}, {%4,%5,%6,%7}, {%8,%9}, {%0,%1,%2,%3};"
        : "+f"(c[0]), "+f"(c[1]), "+f"(c[2]), "+f"(c[3])
        : "r"(a[0]), "r"(a[1]), "r"(a[2]), "r"(a[3]), "r"(b0), "r"(b1));
}

__device__ __forceinline__ void cp16(uint32_t smem_addr, const void* gptr) {
    asm volatile("cp.async.cg.shared.global [%0], [%1], 16;"
                 :: "r"(smem_addr), "l"(gptr) : "memory");
}
__device__ __forceinline__ void cp_commit() {
    asm volatile("cp.async.commit_group;" ::: "memory");
}
template <int N>
__device__ __forceinline__ void cp_wait() {
    asm volatile("cp.async.wait_group %0;" :: "n"(N) : "memory");
}

// ---------------- K0a: tf32 pre-rounding copy (plain) ----------------
__global__ void cvt_tf32_kernel(const float* __restrict__ in,
                                float* __restrict__ out, int n4) {
    int i = blockIdx.x * blockDim.x + threadIdx.x;
    if (i >= n4) return;
    float4 v = ((const float4*)in)[i];
    v.x = rnd_tf32(v.x); v.y = rnd_tf32(v.y);
    v.z = rnd_tf32(v.z); v.w = rnd_tf32(v.w);
    ((float4*)out)[i] = v;
}

// ---------------- K0b: tf32 round + PAIR-PERMUTE copy (feat) --------------
// Within each 8-word block, position u holds original k(u) = (u>>1)+(u&1)*4.
// float4 at positions 4q..4q+3 (q=0,1) holds originals {2q, 2q+4, 2q+1, 2q+5}.
__global__ void cvt_pair_kernel(const float* __restrict__ in,
                                float* __restrict__ out, int n4) {
    int i = blockIdx.x * blockDim.x + threadIdx.x;
    if (i >= n4) return;
    int b8 = (i >> 1) * 8, q = i & 1;
    const float* src = in + b8 + 2 * q;
    float4 v;
    v.x = rnd_tf32(src[0]);
    v.y = rnd_tf32(src[4]);
    v.z = rnd_tf32(src[1]);
    v.w = rnd_tf32(src[5]);
    ((float4*)out)[i] = v;
}

// ---------------- K1: cls_qkv (warp per output, split-K) ----------------
__global__ __launch_bounds__(256)
void cls_qkv_kernel(const float* __restrict__ cls_tokens,
                    const float* __restrict__ Wqkv,
                    const float* __restrict__ bqkv,
                    float* __restrict__ cls_qkv) {
    const int w = blockIdx.x * 8 + (threadIdx.x >> 5);
    const int lane = threadIdx.x & 31;
    const int b = w / C3, o = w - b * C3;
    float s = 0.f;
    #pragma unroll
    for (int k = lane; k < CHN; k += 32)
        s += cls_tokens[b * CHN + k] * Wqkv[(size_t)k * C3 + o];
    #pragma unroll
    for (int d = 16; d >= 1; d >>= 1)
        s += __shfl_xor_sync(0xffffffffu, s, d);
    if (lane == 0) cls_qkv[w] = rnd_tf32(s + bqkv[o]);
}

// ------ tf32 GEMM: 128x128x32, 256 thr, cp.async 3-stage, 2 CTAs/SM -------
// PAIRED=1: A (featc) stored pair-permuted -> A-frags load as LDS.64;
//           B rows fetched in permuted order at cp.async time (kmap).
// PAIRED=0: exact R9 layout/paths.
#define NSTAGE 3

template <int MODE, int PAIRED>
__global__ __launch_bounds__(256, 2)
void tgemm_kernel(const float* __restrict__ A, const float* __restrict__ B,
                  const float* __restrict__ bias, float* __restrict__ Cout,
                  const int* __restrict__ rowmap,
                  int Kdim, int lda, int ldb, int ldc) {
    constexpr int AS_STRIDE = PAIRED ? 40 : 36;
    constexpr int BS_STRIDE = PAIRED ? 132 : 136;
    constexpr int AS_BUF = 128 * AS_STRIDE;
    constexpr int BS_BUF = 32 * BS_STRIDE;

    extern __shared__ float smf[];
    uint32_t* As = (uint32_t*)smf;
    uint32_t* Bs = (uint32_t*)smf + NSTAGE * AS_BUF;

    const int tid  = threadIdx.x;
    const int lane = tid & 31;
    const int warp = tid >> 5;
    const int wm   = warp >> 2;
    const int wn   = warp & 3;
    const int g    = lane >> 2;
    const int t    = lane & 3;

    const int a_row = tid >> 1;
    const int a_k0  = (tid & 1) * 16;
    const float* Aptr = A + (size_t)(blockIdx.y * 128 + a_row) * lda + a_k0;
    const float* Bbase = B + blockIdx.x * 128;

    const uint32_t as_s = (uint32_t)__cvta_generic_to_shared(As + a_row * AS_STRIDE + a_k0);
    const int b_r  = tid >> 5;                       // 0..7
    const int b_kr = PAIRED ? ((b_r >> 1) + (b_r & 1) * 4) : b_r;  // permuted global k-row
    const int b_c4 = tid & 31;
    const uint32_t bs_s = (uint32_t)__cvta_generic_to_shared(Bs + b_r * BS_STRIDE + b_c4 * 4);

    auto issue = [&](int kt, int buf) {
        const float* ag = Aptr + kt * 32;
        uint32_t ad = as_s + buf * (AS_BUF * 4);
        cp16(ad,      ag);
        cp16(ad + 16, ag + 4);
        cp16(ad + 32, ag + 8);
        cp16(ad + 48, ag + 12);
        const float* bg = Bbase + (size_t)(kt * 32 + b_kr) * ldb + b_c4 * 4;
        uint32_t bd = bs_s + buf * (BS_BUF * 4);
        #pragma unroll
        for (int i = 0; i < 4; i++)
            cp16(bd + i * (8 * BS_STRIDE * 4), bg + (size_t)(8 * i) * ldb);
    };

    const int nk = Kdim >> 5;
    issue(0, 0); cp_commit();
    issue(1, 1); cp_commit();

    float c[4][4][4];
    #pragma unroll
    for (int mi = 0; mi < 4; mi++)
        #pragma unroll
        for (int ni = 0; ni < 4; ni++)
            #pragma unroll
            for (int r = 0; r < 4; r++) c[mi][ni][r] = 0.f;

    for (int kt = 0; kt < nk; kt++) {
        const int cur = kt % NSTAGE;
        if (kt + 1 < nk) cp_wait<1>(); else cp_wait<0>();
        __syncthreads();
        if (kt + 2 < nk) { issue(kt + 2, (kt + 2) % NSTAGE); cp_commit(); }

        const uint32_t* asb = As + cur * AS_BUF;
        const uint32_t* bsb = Bs + cur * BS_BUF;
        #pragma unroll
        for (int ks = 0; ks < 4; ks++) {
            const int k0 = ks * 8;
            uint32_t af[4][4], bf[4][2];
            #pragma unroll
            for (int mi = 0; mi < 4; mi++) {
                const int row = wm * 64 + mi * 16 + g;
                if (PAIRED) {
                    // positions k0+2t, k0+2t+1 hold originals k0+t, k0+t+4
                    uint2 lo = *(const uint2*)&asb[(row)     * AS_STRIDE + k0 + 2 * t];
                    uint2 hi = *(const uint2*)&asb[(row + 8) * AS_STRIDE + k0 + 2 * t];
                    af[mi][0] = lo.x; af[mi][1] = hi.x;
                    af[mi][2] = lo.y; af[mi][3] = hi.y;
                } else {
                    af[mi][0] = asb[(row)     * AS_STRIDE + k0 + t];
                    af[mi][1] = asb[(row + 8) * AS_STRIDE + k0 + t];
                    af[mi][2] = asb[(row)     * AS_STRIDE + k0 + t + 4];
                    af[mi][3] = asb[(row + 8) * AS_STRIDE + k0 + t + 4];
                }
            }
            #pragma unroll
            for (int ni = 0; ni < 4; ni++) {
                const int col = wn * 32 + ni * 8 + g;
                if (PAIRED) {
                    // smem row k0+2t holds original k-row k0+t; +1 holds k0+t+4
                    bf[ni][0] = bsb[(k0 + 2 * t)     * BS_STRIDE + col];
                    bf[ni][1] = bsb[(k0 + 2 * t + 1) * BS_STRIDE + col];
                } else {
                    bf[ni][0] = bsb[(k0 + t)     * BS_STRIDE + col];
                    bf[ni][1] = bsb[(k0 + t + 4) * BS_STRIDE + col];
                }
            }
            #pragma unroll
            for (int mi = 0; mi < 4; mi++)
                #pragma unroll
                for (int ni = 0; ni < 4; ni++)
                    mma_tf32(c[mi][ni], af[mi], bf[ni][0], bf[ni][1]);
        }
    }

    float2 bv[4];
    #pragma unroll
    for (int ni = 0; ni < 4; ni++)
        bv[ni] = *(const float2*)&bias[blockIdx.x * 128 + wn * 32 + ni * 8 + t * 2];

    #pragma unroll
    for (int mi = 0; mi < 4; mi++) {
        const int m0 = blockIdx.y * 128 + wm * 64 + mi * 16 + g;
        const int r0 = (MODE == 0) ? rowmap[m0]     : m0;
        const int r1 = (MODE == 0) ? rowmap[m0 + 8] : m0 + 8;
        #pragma unroll
        for (int ni = 0; ni < 4; ni++) {
            const int col = blockIdx.x * 128 + wn * 32 + ni * 8 + t * 2;
            float2 v0 = make_float2(c[mi][ni][0] + bv[ni].x, c[mi][ni][1] + bv[ni].y);
            float2 v1 = make_float2(c[mi][ni][2] + bv[ni].x, c[mi][ni][3] + bv[ni].y);
            if (MODE == 0) {
                v0.x = rnd_tf32(v0.x); v0.y = rnd_tf32(v0.y);
                v1.x = rnd_tf32(v1.x); v1.y = rnd_tf32(v1.y);
            }
            *(float2*)(Cout + (size_t)r0 * ldc + col) = v0;
            *(float2*)(Cout + (size_t)r1 * ldc + col) = v1;
        }
    }
}

#define GEMM_SMEM_P (NSTAGE * (128 * 40 + 32 * 132) * 4)   // 112128
#define GEMM_SMEM_U (NSTAGE * (128 * 36 + 32 * 136) * 4)   // 110592

// ---------------- K3: tensor-core flash attention (identical to R9) --------
#define KT_STRIDE 264
#define VS_STRIDE 72
#define QS_STRIDE 72
#define KT_WORDS (64 * KT_STRIDE)
#define VS_WORDS (264 * VS_STRIDE)
#define QS_WORDS (256 * QS_STRIDE)
#define AT_SMEM ((KT_WORDS + VS_WORDS + QS_WORDS) * 4)   // 217344 bytes

__global__ __launch_bounds__(512)
void attn_tc_kernel(const float* __restrict__ qkv,
                    const float* __restrict__ cls_qkv,
                    const int* __restrict__ order,
                    const int* __restrict__ offset,
                    float* __restrict__ outp,
                    float* __restrict__ cls_out) {
    extern __shared__ uint32_t sm[];
    uint32_t* Kt = sm;
    uint32_t* Vs = sm + KT_WORDS;
    uint32_t* Qs = sm + KT_WORDS + VS_WORDS;

    __shared__ float cq[64];
    __shared__ float cps[257];
    __shared__ float cpart[512];
    __shared__ float cinv;

    const int chunk = blockIdx.x >> 3;
    const int head  = blockIdx.x & 7;
    const int tid   = threadIdx.x;

    const int start = chunk * PSZ;
    const int bid = (start >= offset[0]) + (start >= offset[1]) +
                    (start >= offset[2]) + (start >= offset[3]);
    const float* clsrow = cls_qkv + (size_t)bid * C3;

    for (int e = tid; e < 64 * 7; e += 512) {
        int d = e / 7, k = e % 7;
        Kt[d * KT_STRIDE + 257 + k] = 0;
    }
    for (int e = tid; e < 7 * VS_STRIDE; e += 512)
        Vs[257 * VS_STRIDE + e] = 0;

    for (int key = tid; key < 257; key += 512) {
        const float* base = (key < 256)
            ? qkv + (size_t)(chunk * PSZ + key) * C3 : clsrow;
        #pragma unroll
        for (int d4 = 0; d4 < 16; d4++) {
            float4 kv = *(const float4*)(base + CHN + head * DHEAD + d4 * 4);
            Kt[(d4 * 4 + 0) * KT_STRIDE + key] = __float_as_uint(kv.x);
            Kt[(d4 * 4 + 1) * KT_STRIDE + key] = __float_as_uint(kv.y);
            Kt[(d4 * 4 + 2) * KT_STRIDE + key] = __float_as_uint(kv.z);
            Kt[(d4 * 4 + 3) * KT_STRIDE + key] = __float_as_uint(kv.w);
        }
    }
    for (int e = tid; e < 257 * 16; e += 512) {
        int key = e >> 4, d4 = e & 15;
        const float* base = (key < 256)
            ? qkv + (size_t)(chunk * PSZ + key) * C3 : clsrow;
        float4 vv = *(const float4*)(base + 2 * CHN + head * DHEAD + d4 * 4);
        uint32_t* dst = Vs + key * VS_STRIDE + d4 * 4;
        dst[0] = __float_as_uint(vv.x); dst[1] = __float_as_uint(vv.y);
        dst[2] = __float_as_uint(vv.z); dst[3] = __float_as_uint(vv.w);
    }
    for (int e = tid; e < 256 * 16; e += 512) {
        int i = e >> 4, d4 = e & 15;
        const float* base = qkv + (size_t)(chunk * PSZ + i) * C3;
        float4 qv = *(const float4*)(base + head * DHEAD + d4 * 4);
        uint32_t* dst = Qs + i * QS_STRIDE + d4 * 4;
        dst[0] = f2tf32(qv.x * ATT_SCALE);
        dst[1] = f2tf32(qv.y * ATT_SCALE);
        dst[2] = f2tf32(qv.z * ATT_SCALE);
        dst[3] = f2tf32(qv.w * ATT_SCALE);
    }
    if (tid < 64) cq[tid] = clsrow[head * DHEAD + tid] * ATT_SCALE;
    __syncthreads();

    const int warp = tid >> 5, lane = tid & 31;
    const int g = lane >> 2, t = lane & 3;
    const int mrow = warp * 16;

    uint32_t qf[8][4];
    #pragma unroll
    for (int ks = 0; ks < 8; ks++) {
        qf[ks][0] = Qs[(mrow + g)     * QS_STRIDE + ks * 8 + t];
        qf[ks][1] = Qs[(mrow + g + 8) * QS_STRIDE + ks * 8 + t];
        qf[ks][2] = Qs[(mrow + g)     * QS_STRIDE + ks * 8 + t + 4];
        qf[ks][3] = Qs[(mrow + g + 8) * QS_STRIDE + ks * 8 + t + 4];
    }
    __syncwarp();

    float o[8][4];
    #pragma unroll
    for (int nt = 0; nt < 8; nt++)
        #pragma unroll
        for (int r = 0; r < 4; r++) o[nt][r] = 0.f;
    float m0 = -1e30f, m1 = -1e30f, l0 = 0.f, l1 = 0.f;

    for (int kb = 0; kb < 5; kb++) {
        const int nnt = (kb < 4) ? 8 : 1;
        float s[8][4];
        #pragma unroll
        for (int nt = 0; nt < 8; nt++)
            #pragma unroll
            for (int r = 0; r < 4; r++) s[nt][r] = 0.f;

        #pragma unroll
        for (int ks = 0; ks < 8; ks++) {
            #pragma unroll
            for (int nt = 0; nt < 8; nt++) {
                if (nt >= nnt) break;
                uint32_t b0 = Kt[(ks * 8 + t)     * KT_STRIDE + kb * 64 + nt * 8 + g];
                uint32_t b1 = Kt[(ks * 8 + t + 4) * KT_STRIDE + kb * 64 + nt * 8 + g];
                mma_tf32(s[nt], qf[ks], b0, b1);
            }
        }
        if (kb == 4) {
            if (t != 0) { s[0][0] = -1e30f; s[0][2] = -1e30f; }
            s[0][1] = -1e30f; s[0][3] = -1e30f;
        }

        float mx0 = -1e30f, mx1 = -1e30f;
        #pragma unroll
        for (int nt = 0; nt < 8; nt++) {
            if (nt >= nnt) break;
            mx0 = fmaxf(mx0, fmaxf(s[nt][0], s[nt][1]));
            mx1 = fmaxf(mx1, fmaxf(s[nt][2], s[nt][3]));
        }
        mx0 = fmaxf(mx0, __shfl_xor_sync(0xffffffffu, mx0, 1));
        mx0 = fmaxf(mx0, __shfl_xor_sync(0xffffffffu, mx0, 2));
        mx1 = fmaxf(mx1, __shfl_xor_sync(0xffffffffu, mx1, 1));
        mx1 = fmaxf(mx1, __shfl_xor_sync(0xffffffffu, mx1, 2));
        float nm0 = fmaxf(m0, mx0), nm1 = fmaxf(m1, mx1);
        float f0 = exp2f(m0 - nm0), f1 = exp2f(m1 - nm1);
        m0 = nm0; m1 = nm1; l0 *= f0; l1 *= f1;
        #pragma unroll
        for (int nt = 0; nt < 8; nt++) {
            o[nt][0] *= f0; o[nt][1] *= f0;
            o[nt][2] *= f1; o[nt][3] *= f1;
        }
        #pragma unroll
        for (int nt = 0; nt < 8; nt++) {
            if (nt >= nnt) break;
            float p0 = exp2f(s[nt][0] - m0), p1 = exp2f(s[nt][1] - m0);
            float p2 = exp2f(s[nt][2] - m1), p3 = exp2f(s[nt][3] - m1);
            l0 += p0 + p1; l1 += p2 + p3;
            Qs[(mrow + g)     * QS_STRIDE + nt * 8 + 2 * t]     = f2tf32(p0);
            Qs[(mrow + g)     * QS_STRIDE + nt * 8 + 2 * t + 1] = f2tf32(p1);
            Qs[(mrow + g + 8) * QS_STRIDE + nt * 8 + 2 * t]     = f2tf32(p2);
            Qs[(mrow + g + 8) * QS_STRIDE + nt * 8 + 2 * t + 1] = f2tf32(p3);
        }
        __syncwarp();

        const int nks = (kb < 4) ? 8 : 1;
        #pragma unroll
        for (int ks = 0; ks < 8; ks++) {
            if (ks >= nks) break;
            uint32_t pf[4];
            pf[0] = Qs[(mrow + g)     * QS_STRIDE + ks * 8 + t];
            pf[1] = Qs[(mrow + g + 8) * QS_STRIDE + ks * 8 + t];
            pf[2] = Qs[(mrow + g)     * QS_STRIDE + ks * 8 + t + 4];
            pf[3] = Qs[(mrow + g + 8) * QS_STRIDE + ks * 8 + t + 4];
            #pragma unroll
            for (int nt = 0; nt < 8; nt++) {
                uint32_t b0 = Vs[(kb * 64 + ks * 8 + t)     * VS_STRIDE + nt * 8 + g];
                uint32_t b1 = Vs[(kb * 64 + ks * 8 + t + 4) * VS_STRIDE + nt * 8 + g];
                mma_tf32(o[nt], pf, b0, b1);
            }
        }
        __syncwarp();
    }

    l0 += __shfl_xor_sync(0xffffffffu, l0, 1);
    l0 += __shfl_xor_sync(0xffffffffu, l0, 2);
    l1 += __shfl_xor_sync(0xffffffffu, l1, 1);
    l1 += __shfl_xor_sync(0xffffffffu, l1, 2);
    const float inv0 = 1.f / l0, inv1 = 1.f / l1;

    const int q0 = chunk * PSZ + mrow + g;
    const int dr0 = order[q0];
    const int dr1 = order[q0 + 8];
    #pragma unroll
    for (int nt = 0; nt < 8; nt++) {
        const int col = head * DHEAD + nt * 8 + 2 * t;
        float2 v0 = make_float2(rnd_tf32(o[nt][0] * inv0), rnd_tf32(o[nt][1] * inv0));
        float2 v1 = make_float2(rnd_tf32(o[nt][2] * inv1), rnd_tf32(o[nt][3] * inv1));
        *(float2*)(outp + (size_t)dr0 * CHN + col) = v0;
        *(float2*)(outp + (size_t)dr1 * CHN + col) = v1;
    }

    // ---- cls-query attention epilogue ----
    __syncthreads();
    for (int key = tid; key < 257; key += 512) {
        float s = 0.f;
        #pragma unroll
        for (int d = 0; d < 64; d++)
            s += cq[d] * __uint_as_float(Kt[d * KT_STRIDE + key]);
        cps[key] = s;
    }
    __syncthreads();
    if (tid < 32) {
        float mx = -1e30f;
        for (int j = tid; j < 257; j += 32) mx = fmaxf(mx, cps[j]);
        #pragma unroll
        for (int d = 16; d >= 1; d >>= 1)
            mx = fmaxf(mx, __shfl_xor_sync(0xffffffffu, mx, d));
        float sum = 0.f;
        for (int j = tid; j < 257; j += 32) {
            float p = exp2f(cps[j] - mx);
            cps[j] = p;
            sum += p;
        }
        #pragma unroll
        for (int d = 16; d >= 1; d >>= 1)
            sum += __shfl_xor_sync(0xffffffffu, sum, d);
        if (tid == 0) cinv = 1.f / sum;
    }
    __syncthreads();
    {
        const int d = tid & 63, q = tid >> 6;
        float a = 0.f;
        for (int j = q; j < 257; j += 8)
            a += cps[j] * __uint_as_float(Vs[j * VS_STRIDE + d]);
        cpart[tid] = a;
    }
    __syncthreads();
    if (tid < 64) {
        float a = 0.f;
        #pragma unroll
        for (int q = 0; q < 8; q++) a += cpart[q * 64 + tid];
        cls_out[(size_t)chunk * CHN + head * DHEAD + tid] = a * cinv;
    }
}

// ---------------- K5: cls_feat = per-batch mean of cls_out ------------
__global__ void cls_feat_kernel(const float* __restrict__ cls_out,
                                const int* __restrict__ offset,
                                float* __restrict__ out) {
    int b = blockIdx.x;
    int c = threadIdx.x;
    int o0 = offset[0], o1 = offset[1], o2 = offset[2], o3 = offset[3];
    float s = 0.f, cnt = 0.f;
    for (int ch = 0; ch < NCHUNK; ch++) {
        int start = ch * PSZ;
        int bid = (start >= o0) + (start >= o1) + (start >= o2) + (start >= o3);
        if (bid == b) { s += cls_out[(size_t)ch * CHN + c]; cnt += 1.f; }
    }
    out[(size_t)b * CHN + c] = s / cnt;
}

// ---------------- launch ----------------
extern "C" void kernel_launch(void* const* d_in, const int* in_sizes, int n_in,
                              void* d_out, int out_size) {
    const float* feat       = (const float*)d_in[0];
    const float* cls_tokens = (const float*)d_in[1];
    const float* Wqkv       = (const float*)d_in[2];
    const float* bqkv       = (const float*)d_in[3];
    const float* Wproj      = (const float*)d_in[4];
    const float* bproj      = (const float*)d_in[5];
    const int*   order      = (const int*)d_in[6];
    const int*   inverse    = (const int*)d_in[7];
    const int*   offset     = (const int*)d_in[8];
    float* out = (float*)d_out;

    float *qkv_p, *outp_p, *clsout_p, *clsqkv_p, *featc_p, *wqkvc_p, *wprojc_p;
    cudaGetSymbolAddress((void**)&qkv_p, g_qkv);
    cudaGetSymbolAddress((void**)&outp_p, g_outp);
    cudaGetSymbolAddress((void**)&clsout_p, g_cls_out);
    cudaGetSymbolAddress((void**)&clsqkv_p, g_cls_qkv);
    cudaGetSymbolAddress((void**)&featc_p, g_featc);
    cudaGetSymbolAddress((void**)&wqkvc_p, g_wqkvc);
    cudaGetSymbolAddress((void**)&wprojc_p, g_wprojc);

    cudaFuncSetAttribute((const void*)tgemm_kernel<0, 1>,
                         cudaFuncAttributeMaxDynamicSharedMemorySize, GEMM_SMEM_P);
    cudaFuncSetAttribute((const void*)tgemm_kernel<1, 0>,
                         cudaFuncAttributeMaxDynamicSharedMemorySize, GEMM_SMEM_U);
    cudaFuncSetAttribute(attn_tc_kernel, cudaFuncAttributeMaxDynamicSharedMemorySize, AT_SMEM);

    // K0: tf32 prep — feat pair-permuted, weights plain
    {
        int n4 = NPTS * CHN / 4;
        cvt_pair_kernel<<<(n4 + 255) / 256, 256>>>(feat, featc_p, n4);
        n4 = CHN * C3 / 4;
        cvt_tf32_kernel<<<(n4 + 255) / 256, 256>>>(Wqkv, wqkvc_p, n4);
        n4 = CHN * CHN / 4;
        cvt_tf32_kernel<<<(n4 + 255) / 256, 256>>>(Wproj, wprojc_p, n4);
    }

    // K1: cls qkv (warp-per-output)
    cls_qkv_kernel<<<NBATCH * C3 / 8, 256>>>(cls_tokens, Wqkv, bqkv, clsqkv_p);

    // K2: qkv = feat @ Wqkv + bqkv (PAIRED), scattered by inverse, tf32-rounded
    tgemm_kernel<0, 1><<<dim3(C3 / 128, NPTS / 128), 256, GEMM_SMEM_P>>>(
        featc_p, wqkvc_p, bqkv, qkv_p, inverse, CHN, CHN, C3, C3);

    // K3: flash attention (256 point queries + cls query per block)
    attn_tc_kernel<<<NCHUNK * NHEAD, 512, AT_SMEM>>>(
        qkv_p, clsqkv_p, order, offset, outp_p, clsout_p);

    // K4: feat_out = outp @ Wproj + bproj (UNPAIRED, exact R9 path)
    tgemm_kernel<1, 0><<<dim3(CHN / 128, NPTS / 128), 256, GEMM_SMEM_U>>>(
        outp_p, wprojc_p, bproj, out, nullptr, CHN, CHN, CHN, CHN);

    // K5: cls_feat
    cls_feat_kernel<<<NBATCH, CHN>>>(clsout_p, offset, out + (size_t)NPTS * CHN);
}

// round 16
// speedup vs baseline: 1.2542x; 1.0748x over previous
#include <cuda_runtime.h>
#include <cstdint>
#include <cstddef>

#define NPTS   65536
#define CHN    512
#define C3     1536
#define PSZ    256
#define NHEAD  8
#define DHEAD  64
#define NBATCH 4
#define NCHUNK (NPTS / PSZ)   // 256

// log2(e) folded into the attention scale: softmax uses exp2
#define ATT_SCALE (0.125f * 1.44269504088896340736f)

// ---------------- scratch (device globals: allocation-free) ----------------
__device__ float g_qkv[(size_t)NPTS * C3];       // serialized-order qkv (tf32-rounded)
__device__ float g_outp[(size_t)NPTS * CHN];     // attention out (tf32-rounded)
__device__ float g_featc[(size_t)NPTS * CHN];    // tf32-rounded feat
__device__ float g_wqkvc[(size_t)CHN * C3];      // tf32-rounded Wqkv
__device__ float g_wprojc[(size_t)CHN * CHN];    // tf32-rounded Wproj
__device__ float g_cls_out[NCHUNK * CHN];
__device__ float g_cls_qkv[NBATCH * C3];

__device__ __forceinline__ uint32_t f2tf32(float f) {
    uint32_t u;
    asm("cvt.rna.tf32.f32 %0, %1;" : "=r"(u) : "f"(f));
    return u;
}
__device__ __forceinline__ float rnd_tf32(float f) {
    return __uint_as_float(f2tf32(f));
}

__device__ __forceinline__ void mma_tf32(float* c, const uint32_t* a,
                                         uint32_t b0, uint32_t b1) {
    asm volatile(
        "mma.sync.aligned.m16n8k8.row.col.f32.tf32.tf32.f32 "
        "{%0,%1,%2,%3}, {%4,%5,%6,%7}, {%8,%9}, {%0,%1,%2,%3};"
        : "+f"(c[0]), "+f"(c[1]), "+f"(c[2]), "+f"(c[3])
        : "r"(a[0]), "r"(a[1]), "r"(a[2]), "r"(a[3]), "r"(b0), "r"(b1));
}

__device__ __forceinline__ void cp16(uint32_t smem_addr, const void* gptr) {
    asm volatile("cp.async.cg.shared.global [%0], [%1], 16;"
                 :: "r"(smem_addr), "l"(gptr) : "memory");
}
__device__ __forceinline__ void cp_commit() {
    asm volatile("cp.async.commit_group;" ::: "memory");
}
template <int N>
__device__ __forceinline__ void cp_wait() {
    asm volatile("cp.async.wait_group %0;" :: "n"(N) : "memory");
}

// ---------------- K0: tf32 pre-rounding copy ----------------
__global__ void cvt_tf32_kernel(const float* __restrict__ in,
                                float* __restrict__ out, int n4) {
    int i = blockIdx.x * blockDim.x + threadIdx.x;
    if (i >= n4) return;
    float4 v = ((const float4*)in)[i];
    v.x = rnd_tf32(v.x); v.y = rnd_tf32(v.y);
    v.z = rnd_tf32(v.z); v.w = rnd_tf32(v.w);
    ((float4*)out)[i] = v;
}

// ---------------- K1: cls_qkv (warp per output, split-K) ----------------
__global__ __launch_bounds__(256)
void cls_qkv_kernel(const float* __restrict__ cls_tokens,
                    const float* __restrict__ Wqkv,
                    const float* __restrict__ bqkv,
                    float* __restrict__ cls_qkv) {
    const int w = blockIdx.x * 8 + (threadIdx.x >> 5);
    const int lane = threadIdx.x & 31;
    const int b = w / C3, o = w - b * C3;
    float s = 0.f;
    #pragma unroll
    for (int k = lane; k < CHN; k += 32)
        s += cls_tokens[b * CHN + k] * Wqkv[(size_t)k * C3 + o];
    #pragma unroll
    for (int d = 16; d >= 1; d >>= 1)
        s += __shfl_xor_sync(0xffffffffu, s, d);
    if (lane == 0) cls_qkv[w] = rnd_tf32(s + bqkv[o]);
}

// ------ tf32 GEMM: 128x128x32, 256 thr, cp.async 3-stage, 2 CTAs/SM -------
// EXACT R9 kernel — proven fastest; do not perturb.
#define AS_STRIDE 36
#define BS_STRIDE 136
#define AS_BUF (128 * AS_STRIDE)
#define BS_BUF (32 * BS_STRIDE)
#define NSTAGE 3
#define GEMM_SMEM (NSTAGE * (AS_BUF + BS_BUF) * 4)   // 107520 bytes

template <int MODE>   // 0: scatter rows by rowmap + tf32-round output; 1: direct fp32
__global__ __launch_bounds__(256, 2)
void tgemm_kernel(const float* __restrict__ A, const float* __restrict__ B,
                  const float* __restrict__ bias, float* __restrict__ Cout,
                  const int* __restrict__ rowmap,
                  int Kdim, int lda, int ldb, int ldc) {
    extern __shared__ float smf[];
    uint32_t* As = (uint32_t*)smf;
    uint32_t* Bs = (uint32_t*)smf + NSTAGE * AS_BUF;

    const int tid  = threadIdx.x;
    const int lane = tid & 31;
    const int warp = tid >> 5;
    const int wm   = warp >> 2;
    const int wn   = warp & 3;
    const int g    = lane >> 2;
    const int t    = lane & 3;

    const int a_row = tid >> 1;
    const int a_k0  = (tid & 1) * 16;
    const float* Aptr = A + (size_t)(blockIdx.y * 128 + a_row) * lda + a_k0;
    const float* Bbase = B + blockIdx.x * 128;

    const uint32_t as_s = (uint32_t)__cvta_generic_to_shared(As + a_row * AS_STRIDE + a_k0);
    const int b_r  = tid >> 5;
    const int b_c4 = tid & 31;
    const uint32_t bs_s = (uint32_t)__cvta_generic_to_shared(Bs + b_r * BS_STRIDE + b_c4 * 4);

    auto issue = [&](int kt, int buf) {
        const float* ag = Aptr + kt * 32;
        uint32_t ad = as_s + buf * (AS_BUF * 4);
        cp16(ad,      ag);
        cp16(ad + 16, ag + 4);
        cp16(ad + 32, ag + 8);
        cp16(ad + 48, ag + 12);
        const float* bg = Bbase + (size_t)(kt * 32 + b_r) * ldb + b_c4 * 4;
        uint32_t bd = bs_s + buf * (BS_BUF * 4);
        #pragma unroll
        for (int i = 0; i < 4; i++)
            cp16(bd + i * (8 * BS_STRIDE * 4), bg + (size_t)(8 * i) * ldb);
    };

    const int nk = Kdim >> 5;
    issue(0, 0); cp_commit();
    issue(1, 1); cp_commit();

    float c[4][4][4];
    #pragma unroll
    for (int mi = 0; mi < 4; mi++)
        #pragma unroll
        for (int ni = 0; ni < 4; ni++)
            #pragma unroll
            for (int r = 0; r < 4; r++) c[mi][ni][r] = 0.f;

    for (int kt = 0; kt < nk; kt++) {
        const int cur = kt % NSTAGE;
        if (kt + 1 < nk) cp_wait<1>(); else cp_wait<0>();
        __syncthreads();
        if (kt + 2 < nk) { issue(kt + 2, (kt + 2) % NSTAGE); cp_commit(); }

        const uint32_t* asb = As + cur * AS_BUF;
        const uint32_t* bsb = Bs + cur * BS_BUF;
        #pragma unroll
        for (int ks = 0; ks < 4; ks++) {
            const int k0 = ks * 8;
            uint32_t af[4][4], bf[4][2];
            #pragma unroll
            for (int mi = 0; mi < 4; mi++) {
                const int row = wm * 64 + mi * 16 + g;
                af[mi][0] = asb[(row)     * AS_STRIDE + k0 + t];
                af[mi][1] = asb[(row + 8) * AS_STRIDE + k0 + t];
                af[mi][2] = asb[(row)     * AS_STRIDE + k0 + t + 4];
                af[mi][3] = asb[(row + 8) * AS_STRIDE + k0 + t + 4];
            }
            #pragma unroll
            for (int ni = 0; ni < 4; ni++) {
                const int col = wn * 32 + ni * 8 + g;
                bf[ni][0] = bsb[(k0 + t)     * BS_STRIDE + col];
                bf[ni][1] = bsb[(k0 + t + 4) * BS_STRIDE + col];
            }
            #pragma unroll
            for (int mi = 0; mi < 4; mi++)
                #pragma unroll
                for (int ni = 0; ni < 4; ni++)
                    mma_tf32(c[mi][ni], af[mi], bf[ni][0], bf[ni][1]);
        }
    }

    float2 bv[4];
    #pragma unroll
    for (int ni = 0; ni < 4; ni++)
        bv[ni] = *(const float2*)&bias[blockIdx.x * 128 + wn * 32 + ni * 8 + t * 2];

    #pragma unroll
    for (int mi = 0; mi < 4; mi++) {
        const int m0 = blockIdx.y * 128 + wm * 64 + mi * 16 + g;
        const int r0 = (MODE == 0) ? rowmap[m0]     : m0;
        const int r1 = (MODE == 0) ? rowmap[m0 + 8] : m0 + 8;
        #pragma unroll
        for (int ni = 0; ni < 4; ni++) {
            const int col = blockIdx.x * 128 + wn * 32 + ni * 8 + t * 2;
            float2 v0 = make_float2(c[mi][ni][0] + bv[ni].x, c[mi][ni][1] + bv[ni].y);
            float2 v1 = make_float2(c[mi][ni][2] + bv[ni].x, c[mi][ni][3] + bv[ni].y);
            if (MODE == 0) {
                v0.x = rnd_tf32(v0.x); v0.y = rnd_tf32(v0.y);
                v1.x = rnd_tf32(v1.x); v1.y = rnd_tf32(v1.y);
            }
            *(float2*)(Cout + (size_t)r0 * ldc + col) = v0;
            *(float2*)(Cout + (size_t)r1 * ldc + col) = v1;
        }
    }
}

// ---------------- K3: tensor-core flash attention ----------
// Block = 512 thr (16 warps), one block per (chunk, head); 256 queries/block.
// Q pre-scaled by 0.125*log2e -> softmax via exp2. V fill uses cp.async.
#define KT_STRIDE 264
#define VS_STRIDE 72
#define QS_STRIDE 72
#define KT_WORDS (64 * KT_STRIDE)
#define VS_WORDS (264 * VS_STRIDE)
#define QS_WORDS (256 * QS_STRIDE)
#define AT_SMEM ((KT_WORDS + VS_WORDS + QS_WORDS) * 4)   // 217344 bytes

__global__ __launch_bounds__(512)
void attn_tc_kernel(const float* __restrict__ qkv,
                    const float* __restrict__ cls_qkv,
                    const int* __restrict__ order,
                    const int* __restrict__ offset,
                    float* __restrict__ outp,
                    float* __restrict__ cls_out) {
    extern __shared__ uint32_t sm[];
    uint32_t* Kt = sm;
    uint32_t* Vs = sm + KT_WORDS;
    uint32_t* Qs = sm + KT_WORDS + VS_WORDS;

    __shared__ float cq[64];
    __shared__ float cps[257];
    __shared__ float cpart[512];
    __shared__ float cinv;

    const int chunk = blockIdx.x >> 3;
    const int head  = blockIdx.x & 7;
    const int tid   = threadIdx.x;

    const int start = chunk * PSZ;
    const int bid = (start >= offset[0]) + (start >= offset[1]) +
                    (start >= offset[2]) + (start >= offset[3]);
    const float* clsrow = cls_qkv + (size_t)bid * C3;

    // V: raw copy -> cp.async (16B aligned both sides), issued FIRST so the
    // K-transpose and Q-scale fills below overlap its in-flight traffic.
    {
        const uint32_t vs_base = (uint32_t)__cvta_generic_to_shared(Vs);
        for (int e = tid; e < 257 * 16; e += 512) {
            int key = e >> 4, d4 = e & 15;
            const float* src = (key < 256)
                ? qkv + (size_t)(chunk * PSZ + key) * C3 + 2 * CHN + head * DHEAD + d4 * 4
                : clsrow + 2 * CHN + head * DHEAD + d4 * 4;
            cp16(vs_base + (uint32_t)(key * VS_STRIDE + d4 * 4) * 4, src);
        }
        cp_commit();
    }

    // zero pad: Kt cols 257..263, Vs rows 257..263
    for (int e = tid; e < 64 * 7; e += 512) {
        int d = e / 7, k = e % 7;
        Kt[d * KT_STRIDE + 257 + k] = 0;
    }
    for (int e = tid; e < 7 * VS_STRIDE; e += 512)
        Vs[257 * VS_STRIDE + e] = 0;

    // K: one key per thread, transposed store
    for (int key = tid; key < 257; key += 512) {
        const float* base = (key < 256)
            ? qkv + (size_t)(chunk * PSZ + key) * C3 : clsrow;
        #pragma unroll
        for (int d4 = 0; d4 < 16; d4++) {
            float4 kv = *(const float4*)(base + CHN + head * DHEAD + d4 * 4);
            Kt[(d4 * 4 + 0) * KT_STRIDE + key] = __float_as_uint(kv.x);
            Kt[(d4 * 4 + 1) * KT_STRIDE + key] = __float_as_uint(kv.y);
            Kt[(d4 * 4 + 2) * KT_STRIDE + key] = __float_as_uint(kv.z);
            Kt[(d4 * 4 + 3) * KT_STRIDE + key] = __float_as_uint(kv.w);
        }
    }
    // Q: fold 0.125*log2e, re-round to tf32
    for (int e = tid; e < 256 * 16; e += 512) {
        int i = e >> 4, d4 = e & 15;
        const float* base = qkv + (size_t)(chunk * PSZ + i) * C3;
        float4 qv = *(const float4*)(base + head * DHEAD + d4 * 4);
        uint32_t* dst = Qs + i * QS_STRIDE + d4 * 4;
        dst[0] = f2tf32(qv.x * ATT_SCALE);
        dst[1] = f2tf32(qv.y * ATT_SCALE);
        dst[2] = f2tf32(qv.z * ATT_SCALE);
        dst[3] = f2tf32(qv.w * ATT_SCALE);
    }
    if (tid < 64) cq[tid] = clsrow[head * DHEAD + tid] * ATT_SCALE;
    cp_wait<0>();
    __syncthreads();

    const int warp = tid >> 5, lane = tid & 31;
    const int g = lane >> 2, t = lane & 3;
    const int mrow = warp * 16;

    uint32_t qf[8][4];
    #pragma unroll
    for (int ks = 0; ks < 8; ks++) {
        qf[ks][0] = Qs[(mrow + g)     * QS_STRIDE + ks * 8 + t];
        qf[ks][1] = Qs[(mrow + g + 8) * QS_STRIDE + ks * 8 + t];
        qf[ks][2] = Qs[(mrow + g)     * QS_STRIDE + ks * 8 + t + 4];
        qf[ks][3] = Qs[(mrow + g + 8) * QS_STRIDE + ks * 8 + t + 4];
    }
    __syncwarp();

    float o[8][4];
    #pragma unroll
    for (int nt = 0; nt < 8; nt++)
        #pragma unroll
        for (int r = 0; r < 4; r++) o[nt][r] = 0.f;
    float m0 = -1e30f, m1 = -1e30f, l0 = 0.f, l1 = 0.f;

    for (int kb = 0; kb < 5; kb++) {
        const int nnt = (kb < 4) ? 8 : 1;
        float s[8][4];
        #pragma unroll
        for (int nt = 0; nt < 8; nt++)
            #pragma unroll
            for (int r = 0; r < 4; r++) s[nt][r] = 0.f;

        #pragma unroll
        for (int ks = 0; ks < 8; ks++) {
            #pragma unroll
            for (int nt = 0; nt < 8; nt++) {
                if (nt >= nnt) break;
                uint32_t b0 = Kt[(ks * 8 + t)     * KT_STRIDE + kb * 64 + nt * 8 + g];
                uint32_t b1 = Kt[(ks * 8 + t + 4) * KT_STRIDE + kb * 64 + nt * 8 + g];
                mma_tf32(s[nt], qf[ks], b0, b1);
            }
        }
        if (kb == 4) {
            if (t != 0) { s[0][0] = -1e30f; s[0][2] = -1e30f; }
            s[0][1] = -1e30f; s[0][3] = -1e30f;
        }

        float mx0 = -1e30f, mx1 = -1e30f;
        #pragma unroll
        for (int nt = 0; nt < 8; nt++) {
            if (nt >= nnt) break;
            mx0 = fmaxf(mx0, fmaxf(s[nt][0], s[nt][1]));
            mx1 = fmaxf(mx1, fmaxf(s[nt][2], s[nt][3]));
        }
        mx0 = fmaxf(mx0, __shfl_xor_sync(0xffffffffu, mx0, 1));
        mx0 = fmaxf(mx0, __shfl_xor_sync(0xffffffffu, mx0, 2));
        mx1 = fmaxf(mx1, __shfl_xor_sync(0xffffffffu, mx1, 1));
        mx1 = fmaxf(mx1, __shfl_xor_sync(0xffffffffu, mx1, 2));
        float nm0 = fmaxf(m0, mx0), nm1 = fmaxf(m1, mx1);
        float f0 = exp2f(m0 - nm0), f1 = exp2f(m1 - nm1);
        m0 = nm0; m1 = nm1; l0 *= f0; l1 *= f1;
        #pragma unroll
        for (int nt = 0; nt < 8; nt++) {
            o[nt][0] *= f0; o[nt][1] *= f0;
            o[nt][2] *= f1; o[nt][3] *= f1;
        }
        #pragma unroll
        for (int nt = 0; nt < 8; nt++) {
            if (nt >= nnt) break;
            float p0 = exp2f(s[nt][0] - m0), p1 = exp2f(s[nt][1] - m0);
            float p2 = exp2f(s[nt][2] - m1), p3 = exp2f(s[nt][3] - m1);
            l0 += p0 + p1; l1 += p2 + p3;
            Qs[(mrow + g)     * QS_STRIDE + nt * 8 + 2 * t]     = f2tf32(p0);
            Qs[(mrow + g)     * QS_STRIDE + nt * 8 + 2 * t + 1] = f2tf32(p1);
            Qs[(mrow + g + 8) * QS_STRIDE + nt * 8 + 2 * t]     = f2tf32(p2);
            Qs[(mrow + g + 8) * QS_STRIDE + nt * 8 + 2 * t + 1] = f2tf32(p3);
        }
        __syncwarp();

        const int nks = (kb < 4) ? 8 : 1;
        #pragma unroll
        for (int ks = 0; ks < 8; ks++) {
            if (ks >= nks) break;
            uint32_t pf[4];
            pf[0] = Qs[(mrow + g)     * QS_STRIDE + ks * 8 + t];
            pf[1] = Qs[(mrow + g + 8) * QS_STRIDE + ks * 8 + t];
            pf[2] = Qs[(mrow + g)     * QS_STRIDE + ks * 8 + t + 4];
            pf[3] = Qs[(mrow + g + 8) * QS_STRIDE + ks * 8 + t + 4];
            #pragma unroll
            for (int nt = 0; nt < 8; nt++) {
                uint32_t b0 = Vs[(kb * 64 + ks * 8 + t)     * VS_STRIDE + nt * 8 + g];
                uint32_t b1 = Vs[(kb * 64 + ks * 8 + t + 4) * VS_STRIDE + nt * 8 + g];
                mma_tf32(o[nt], pf, b0, b1);
            }
        }
        __syncwarp();
    }

    l0 += __shfl_xor_sync(0xffffffffu, l0, 1);
    l0 += __shfl_xor_sync(0xffffffffu, l0, 2);
    l1 += __shfl_xor_sync(0xffffffffu, l1, 1);
    l1 += __shfl_xor_sync(0xffffffffu, l1, 2);
    const float inv0 = 1.f / l0, inv1 = 1.f / l1;

    const int q0 = chunk * PSZ + mrow + g;
    const int dr0 = order[q0];
    const int dr1 = order[q0 + 8];
    #pragma unroll
    for (int nt = 0; nt < 8; nt++) {
        const int col = head * DHEAD + nt * 8 + 2 * t;
        float2 v0 = make_float2(rnd_tf32(o[nt][0] * inv0), rnd_tf32(o[nt][1] * inv0));
        float2 v1 = make_float2(rnd_tf32(o[nt][2] * inv1), rnd_tf32(o[nt][3] * inv1));
        *(float2*)(outp + (size_t)dr0 * CHN + col) = v0;
        *(float2*)(outp + (size_t)dr1 * CHN + col) = v1;
    }

    // ---- cls-query attention epilogue (K/V still in smem) ----
    __syncthreads();
    for (int key = tid; key < 257; key += 512) {
        float s = 0.f;
        #pragma unroll
        for (int d = 0; d < 64; d++)
            s += cq[d] * __uint_as_float(Kt[d * KT_STRIDE + key]);
        cps[key] = s;
    }
    __syncthreads();
    if (tid < 32) {
        float mx = -1e30f;
        for (int j = tid; j < 257; j += 32) mx = fmaxf(mx, cps[j]);
        #pragma unroll
        for (int d = 16; d >= 1; d >>= 1)
            mx = fmaxf(mx, __shfl_xor_sync(0xffffffffu, mx, d));
        float sum = 0.f;
        for (int j = tid; j < 257; j += 32) {
            float p = exp2f(cps[j] - mx);
            cps[j] = p;
            sum += p;
        }
        #pragma unroll
        for (int d = 16; d >= 1; d >>= 1)
            sum += __shfl_xor_sync(0xffffffffu, sum, d);
        if (tid == 0) cinv = 1.f / sum;
    }
    __syncthreads();
    {
        const int d = tid & 63, q = tid >> 6;
        float a = 0.f;
        for (int j = q; j < 257; j += 8)
            a += cps[j] * __uint_as_float(Vs[j * VS_STRIDE + d]);
        cpart[tid] = a;
    }
    __syncthreads();
    if (tid < 64) {
        float a = 0.f;
        #pragma unroll
        for (int q = 0; q < 8; q++) a += cpart[q * 64 + tid];
        cls_out[(size_t)chunk * CHN + head * DHEAD + tid] = a * cinv;
    }
}

// ---------------- K5: cls_feat (4 independent accumulation chains) ---------
__global__ void cls_feat_kernel(const float* __restrict__ cls_out,
                                const int* __restrict__ offset,
                                float* __restrict__ out) {
    int b = blockIdx.x;
    int c = threadIdx.x;
    int o0 = offset[0], o1 = offset[1], o2 = offset[2], o3 = offset[3];
    float s0 = 0.f, s1 = 0.f, s2 = 0.f, s3 = 0.f, cnt = 0.f;
    for (int ch = 0; ch < NCHUNK; ch += 4) {
        int st0 = ch * PSZ, st1 = st0 + PSZ, st2 = st1 + PSZ, st3 = st2 + PSZ;
        int b0 = (st0 >= o0) + (st0 >= o1) + (st0 >= o2) + (st0 >= o3);
        int b1 = (st1 >= o0) + (st1 >= o1) + (st1 >= o2) + (st1 >= o3);
        int b2 = (st2 >= o0) + (st2 >= o1) + (st2 >= o2) + (st2 >= o3);
        int b3 = (st3 >= o0) + (st3 >= o1) + (st3 >= o2) + (st3 >= o3);
        if (b0 == b) { s0 += cls_out[(size_t)(ch)     * CHN + c]; cnt += 1.f; }
        if (b1 == b) { s1 += cls_out[(size_t)(ch + 1) * CHN + c]; cnt += 1.f; }
        if (b2 == b) { s2 += cls_out[(size_t)(ch + 2) * CHN + c]; cnt += 1.f; }
        if (b3 == b) { s3 += cls_out[(size_t)(ch + 3) * CHN + c]; cnt += 1.f; }
    }
    out[(size_t)b * CHN + c] = ((s0 + s1) + (s2 + s3)) / cnt;
}

// ---------------- launch ----------------
extern "C" void kernel_launch(void* const* d_in, const int* in_sizes, int n_in,
                              void* d_out, int out_size) {
    const float* feat       = (const float*)d_in[0];
    const float* cls_tokens = (const float*)d_in[1];
    const float* Wqkv       = (const float*)d_in[2];
    const float* bqkv       = (const float*)d_in[3];
    const float* Wproj      = (const float*)d_in[4];
    const float* bproj      = (const float*)d_in[5];
    const int*   order      = (const int*)d_in[6];
    const int*   inverse    = (const int*)d_in[7];
    const int*   offset     = (const int*)d_in[8];
    float* out = (float*)d_out;

    float *qkv_p, *outp_p, *clsout_p, *clsqkv_p, *featc_p, *wqkvc_p, *wprojc_p;
    cudaGetSymbolAddress((void**)&qkv_p, g_qkv);
    cudaGetSymbolAddress((void**)&outp_p, g_outp);
    cudaGetSymbolAddress((void**)&clsout_p, g_cls_out);
    cudaGetSymbolAddress((void**)&clsqkv_p, g_cls_qkv);
    cudaGetSymbolAddress((void**)&featc_p, g_featc);
    cudaGetSymbolAddress((void**)&wqkvc_p, g_wqkvc);
    cudaGetSymbolAddress((void**)&wprojc_p, g_wprojc);

    cudaFuncSetAttribute(tgemm_kernel<0>, cudaFuncAttributeMaxDynamicSharedMemorySize, GEMM_SMEM);
    cudaFuncSetAttribute(tgemm_kernel<1>, cudaFuncAttributeMaxDynamicSharedMemorySize, GEMM_SMEM);
    cudaFuncSetAttribute(attn_tc_kernel, cudaFuncAttributeMaxDynamicSharedMemorySize, AT_SMEM);

    // K0: tf32 pre-rounding copies
    {
        int n4 = NPTS * CHN / 4;
        cvt_tf32_kernel<<<(n4 + 255) / 256, 256>>>(feat, featc_p, n4);
        n4 = CHN * C3 / 4;
        cvt_tf32_kernel<<<(n4 + 255) / 256, 256>>>(Wqkv, wqkvc_p, n4);
        n4 = CHN * CHN / 4;
        cvt_tf32_kernel<<<(n4 + 255) / 256, 256>>>(Wproj, wprojc_p, n4);
    }

    // K1: cls qkv (warp-per-output)
    cls_qkv_kernel<<<NBATCH * C3 / 8, 256>>>(cls_tokens, Wqkv, bqkv, clsqkv_p);

    // K2: qkv = feat @ Wqkv + bqkv, scattered by inverse, tf32-rounded output
    tgemm_kernel<0><<<dim3(C3 / 128, NPTS / 128), 256, GEMM_SMEM>>>(
        featc_p, wqkvc_p, bqkv, qkv_p, inverse, CHN, CHN, C3, C3);

    // K3: flash attention (256 point queries + cls query per block)
    attn_tc_kernel<<<NCHUNK * NHEAD, 512, AT_SMEM>>>(
        qkv_p, clsqkv_p, order, offset, outp_p, clsout_p);

    // K4: feat_out = outp @ Wproj + bproj
    tgemm_kernel<1><<<dim3(CHN / 128, NPTS / 128), 256, GEMM_SMEM>>>(
        outp_p, wprojc_p, bproj, out, nullptr, CHN, CHN, CHN, CHN);

    // K5: cls_feat
    cls_feat_kernel<<<NBATCH, CHN>>>(clsout_p, offset, out + (size_t)NPTS * CHN);
}